// round 4
// baseline (speedup 1.0000x reference)
#include <cuda_runtime.h>
#include <math.h>

#define NB 512   // batch
#define NL 128   // context length
#define ND 512   // embed dim

// Scratch (static device globals — no allocation in kernel_launch)
__device__ float g_C[(size_t)NB * NL * ND];   // 134 MB: C = gather(E,t1) @ att_mat
__device__ float g_inv_na[NB];
__device__ float g_inv_nb[NB];
__device__ float g_rows[NB * NL];
__device__ float g_cols[NB * NL];

union F2 { float2 f; unsigned long long u; };

// ---------------------------------------------------------------------------
// Kernel 1: per-batch Frobenius norms of gathered context embeddings
// ---------------------------------------------------------------------------
__global__ __launch_bounds__(256) void norms_kernel(
    const int* __restrict__ t1c, const int* __restrict__ t2c,
    const float* __restrict__ E)
{
    const int b = blockIdx.x, tid = threadIdx.x;
    float s1 = 0.f, s2 = 0.f;
    for (int l = 0; l < NL; l++) {
        const float* r1 = E + (size_t)t1c[b * NL + l] * ND;
        const float* r2 = E + (size_t)t2c[b * NL + l] * ND;
        float a0 = r1[tid], a1 = r1[tid + 256];
        s1 += a0 * a0 + a1 * a1;
        float c0 = r2[tid], c1 = r2[tid + 256];
        s2 += c0 * c0 + c1 * c1;
    }
    __shared__ float sh1[8], sh2[8];
    #pragma unroll
    for (int o = 16; o; o >>= 1) {
        s1 += __shfl_xor_sync(0xffffffffu, s1, o);
        s2 += __shfl_xor_sync(0xffffffffu, s2, o);
    }
    if ((tid & 31) == 0) { sh1[tid >> 5] = s1; sh2[tid >> 5] = s2; }
    __syncthreads();
    if (tid < 8) {
        s1 = sh1[tid]; s2 = sh2[tid];
        #pragma unroll
        for (int o = 4; o; o >>= 1) {
            s1 += __shfl_xor_sync(0xffu, s1, o);
            s2 += __shfl_xor_sync(0xffu, s2, o);
        }
        if (tid == 0) { g_inv_na[b] = rsqrtf(s1); g_inv_nb[b] = rsqrtf(s2); }
    }
}

// ---------------------------------------------------------------------------
// Kernel 2: GEMM1 — C[i,:] = E[idx[i],:] @ M     (one big 65536x512x512 GEMM)
// 128x128 tile, BK=16, 256 threads, 8x8 per thread via packed fma.rn.f32x2
// ---------------------------------------------------------------------------
__global__ __launch_bounds__(256) void gemm1_kernel(
    const int* __restrict__ idx, const float* __restrict__ E,
    const float* __restrict__ M)
{
    __shared__ float As[16][128];
    __shared__ float Bs[16][128];
    const int tid = threadIdx.x;
    const int tx = tid & 15, ty = tid >> 4;
    const int m0 = blockIdx.y * 128, n0 = blockIdx.x * 128;
    const int lr = tid >> 1, lk = (tid & 1) * 8;   // A-tile loader: row, k-offset
    const int bkr = tid >> 4, bc = (tid & 15) * 8; // B-tile loader: k-row, col
    const float* arow = E + (size_t)idx[m0 + lr] * ND;

    F2 acc[8][4];
    #pragma unroll
    for (int i = 0; i < 8; i++)
        #pragma unroll
        for (int j = 0; j < 4; j++) acc[i][j].u = 0ull;

    for (int k0 = 0; k0 < ND; k0 += 16) {
        float4 a0 = *reinterpret_cast<const float4*>(arow + k0 + lk);
        float4 a1 = *reinterpret_cast<const float4*>(arow + k0 + lk + 4);
        const float* bptr = M + (size_t)(k0 + bkr) * ND + n0 + bc;
        float4 b0 = *reinterpret_cast<const float4*>(bptr);
        float4 b1 = *reinterpret_cast<const float4*>(bptr + 4);
        __syncthreads();
        As[lk + 0][lr] = a0.x; As[lk + 1][lr] = a0.y;
        As[lk + 2][lr] = a0.z; As[lk + 3][lr] = a0.w;
        As[lk + 4][lr] = a1.x; As[lk + 5][lr] = a1.y;
        As[lk + 6][lr] = a1.z; As[lk + 7][lr] = a1.w;
        *reinterpret_cast<float4*>(&Bs[bkr][bc]) = b0;
        *reinterpret_cast<float4*>(&Bs[bkr][bc + 4]) = b1;
        __syncthreads();
        #pragma unroll
        for (int k = 0; k < 16; k++) {
            F2 bp[4];
            const float2* bsp = reinterpret_cast<const float2*>(&Bs[k][tx * 8]);
            #pragma unroll
            for (int j = 0; j < 4; j++) bp[j].f = bsp[j];
            #pragma unroll
            for (int i = 0; i < 8; i++) {
                float av = As[k][ty * 8 + i];
                F2 ap; ap.f.x = av; ap.f.y = av;
                #pragma unroll
                for (int j = 0; j < 4; j++)
                    asm("fma.rn.f32x2 %0, %1, %2, %0;"
                        : "+l"(acc[i][j].u) : "l"(ap.u), "l"(bp[j].u));
            }
        }
    }
    #pragma unroll
    for (int i = 0; i < 8; i++) {
        float* crow = g_C + (size_t)(m0 + ty * 8 + i) * ND + n0 + tx * 8;
        #pragma unroll
        for (int j = 0; j < 4; j++)
            *reinterpret_cast<float2*>(crow + 2 * j) = acc[i][j].f;
    }
}

// ---------------------------------------------------------------------------
// Kernel 3: GEMM2 + tanh — S[b] = tanh(scale_b * C[b] @ gather(E,t2[b])^T)
// One block per batch: 128x128 output, K=512
// ---------------------------------------------------------------------------
__global__ __launch_bounds__(256) void gemm2_kernel(
    const int* __restrict__ idx2, const float* __restrict__ E,
    float* __restrict__ outS)
{
    __shared__ float As[16][128];
    __shared__ float Bs[16][128];
    const int b = blockIdx.x, tid = threadIdx.x;
    const int tx = tid & 15, ty = tid >> 4;
    const int lr = tid >> 1, lk = (tid & 1) * 8;
    const float* arow = g_C + ((size_t)b * NL + lr) * ND;
    const float* brow = E + (size_t)idx2[b * NL + lr] * ND;

    F2 acc[8][4];
    #pragma unroll
    for (int i = 0; i < 8; i++)
        #pragma unroll
        for (int j = 0; j < 4; j++) acc[i][j].u = 0ull;

    for (int k0 = 0; k0 < ND; k0 += 16) {
        float4 a0 = *reinterpret_cast<const float4*>(arow + k0 + lk);
        float4 a1 = *reinterpret_cast<const float4*>(arow + k0 + lk + 4);
        float4 b0 = *reinterpret_cast<const float4*>(brow + k0 + lk);
        float4 b1 = *reinterpret_cast<const float4*>(brow + k0 + lk + 4);
        __syncthreads();
        As[lk + 0][lr] = a0.x; As[lk + 1][lr] = a0.y;
        As[lk + 2][lr] = a0.z; As[lk + 3][lr] = a0.w;
        As[lk + 4][lr] = a1.x; As[lk + 5][lr] = a1.y;
        As[lk + 6][lr] = a1.z; As[lk + 7][lr] = a1.w;
        Bs[lk + 0][lr] = b0.x; Bs[lk + 1][lr] = b0.y;
        Bs[lk + 2][lr] = b0.z; Bs[lk + 3][lr] = b0.w;
        Bs[lk + 4][lr] = b1.x; Bs[lk + 5][lr] = b1.y;
        Bs[lk + 6][lr] = b1.z; Bs[lk + 7][lr] = b1.w;
        __syncthreads();
        #pragma unroll
        for (int k = 0; k < 16; k++) {
            F2 bp[4];
            const float2* bsp = reinterpret_cast<const float2*>(&Bs[k][tx * 8]);
            #pragma unroll
            for (int j = 0; j < 4; j++) bp[j].f = bsp[j];
            #pragma unroll
            for (int i = 0; i < 8; i++) {
                float av = As[k][ty * 8 + i];
                F2 ap; ap.f.x = av; ap.f.y = av;
                #pragma unroll
                for (int j = 0; j < 4; j++)
                    asm("fma.rn.f32x2 %0, %1, %2, %0;"
                        : "+l"(acc[i][j].u) : "l"(ap.u), "l"(bp[j].u));
            }
        }
    }
    const float scale = g_inv_na[b] * g_inv_nb[b];
    #pragma unroll
    for (int i = 0; i < 8; i++) {
        float* srow = outS + (size_t)b * NL * NL + (ty * 8 + i) * NL + tx * 8;
        #pragma unroll
        for (int j = 0; j < 4; j++) {
            srow[2 * j + 0] = tanhf(acc[i][j].f.x * scale);
            srow[2 * j + 1] = tanhf(acc[i][j].f.y * scale);
        }
    }
}

// ---------------------------------------------------------------------------
// Kernel 4: row/col means of S + softmax over L
// ---------------------------------------------------------------------------
__global__ __launch_bounds__(128) void softmax_kernel(const float* __restrict__ S)
{
    const int b = blockIdx.x, t = threadIdx.x;
    const float* Sb = S + (size_t)b * NL * NL;
    float rs = 0.f, cs = 0.f;
    for (int i = 0; i < NL; i++) {
        rs += Sb[t * NL + i];   // row t, mean over m (axis 2)
        cs += Sb[i * NL + t];   // col t, mean over l (axis 1)
    }
    rs *= (1.0f / NL);
    cs *= (1.0f / NL);

    __shared__ float buf[128];
    // softmax(rows)
    buf[t] = rs; __syncthreads();
    for (int s = 64; s; s >>= 1) { if (t < s) buf[t] = fmaxf(buf[t], buf[t + s]); __syncthreads(); }
    float mx = buf[0]; __syncthreads();
    float er = expf(rs - mx);
    buf[t] = er; __syncthreads();
    for (int s = 64; s; s >>= 1) { if (t < s) buf[t] += buf[t + s]; __syncthreads(); }
    g_rows[b * NL + t] = er / buf[0];
    __syncthreads();
    // softmax(cols)
    buf[t] = cs; __syncthreads();
    for (int s = 64; s; s >>= 1) { if (t < s) buf[t] = fmaxf(buf[t], buf[t + s]); __syncthreads(); }
    mx = buf[0]; __syncthreads();
    float ec = expf(cs - mx);
    buf[t] = ec; __syncthreads();
    for (int s = 64; s; s >>= 1) { if (t < s) buf[t] += buf[t + s]; __syncthreads(); }
    g_cols[b * NL + t] = ec / buf[0];
}

// ---------------------------------------------------------------------------
// Kernel 5: newA/newB weighted re-gather + logits
// ---------------------------------------------------------------------------
__global__ __launch_bounds__(256) void final_kernel(
    const int* __restrict__ t1c, const int* __restrict__ t2c,
    const float* __restrict__ E, const float* __restrict__ w,
    const float* __restrict__ bp, float* __restrict__ out)
{
    const int b = blockIdx.x, tid = threadIdx.x;
    __shared__ float rw[NL], cw[NL];
    if (tid < NL) { rw[tid] = g_rows[b * NL + tid]; cw[tid] = g_cols[b * NL + tid]; }
    __syncthreads();
    float nA0 = 0.f, nA1 = 0.f, nB0 = 0.f, nB1 = 0.f;
    for (int l = 0; l < NL; l++) {
        const float* r1 = E + (size_t)t1c[b * NL + l] * ND;
        const float* r2 = E + (size_t)t2c[b * NL + l] * ND;
        float wr = rw[l], wc = cw[l];
        nA0 += wr * r1[tid];        nA1 += wr * r1[tid + 256];
        nB0 += wc * r2[tid];        nB1 += wc * r2[tid + 256];
    }
    const float scale = g_inv_na[b] * g_inv_nb[b];
    float part = (nA0 * nB0 * w[tid] + nA1 * nB1 * w[tid + 256]) * scale;
    __shared__ float sh[8];
    #pragma unroll
    for (int o = 16; o; o >>= 1) part += __shfl_xor_sync(0xffffffffu, part, o);
    if ((tid & 31) == 0) sh[tid >> 5] = part;
    __syncthreads();
    if (tid < 8) {
        part = sh[tid];
        #pragma unroll
        for (int o = 4; o; o >>= 1) part += __shfl_xor_sync(0xffu, part, o);
        if (tid == 0) out[b] = part + bp[0];
    }
}

// ---------------------------------------------------------------------------
extern "C" void kernel_launch(void* const* d_in, const int* in_sizes, int n_in,
                              void* d_out, int out_size)
{
    (void)in_sizes; (void)n_in; (void)out_size;
    // inputs: 0=t1s 1=t2s (unused, dead code in reference) 2=t1_contexts
    // 3=t2_contexts 4=embed_table 5=att_mat 6=w_pred 7=b_pred
    const int*   t1c = (const int*)d_in[2];
    const int*   t2c = (const int*)d_in[3];
    const float* E   = (const float*)d_in[4];
    const float* M   = (const float*)d_in[5];
    const float* w   = (const float*)d_in[6];
    const float* bp  = (const float*)d_in[7];
    float* out  = (float*)d_out;
    float* outS = out + NB;   // output = concat(logits[512], S[512*128*128])

    norms_kernel<<<NB, 256>>>(t1c, t2c, E);
    gemm1_kernel<<<dim3(ND / 128, NB * NL / 128), 256>>>(t1c, E, M);
    gemm2_kernel<<<NB, 256>>>(t2c, E, outS);
    softmax_kernel<<<NB, 128>>>(outS);
    final_kernel<<<NB, 256>>>(t1c, t2c, E, w, bp, out);
}